// round 6
// baseline (speedup 1.0000x reference)
#include <cuda_runtime.h>
#include <cuda_fp16.h>
#include <stdint.h>

// Problem constants
#define NN   20000
#define RR   11
#define BB   8
#define IND  300
#define OUTD 256
#define EE   640000
#define KK   (BB*IND)            // 2400
#define NSTAGE 75                // KK/32
#define NTILE  313               // ceil(NN/64)

// -------- device scratch --------
__device__ int      g_cnt2[RR*NN];
__device__ int      g_off2[RR*NN+1];
__device__ int      g_cur2[RR*NN];
__device__ uint32_t g_e32[EE];                       // dst | rel<<16
__device__ __half   g_F16[(size_t)NN*IND];           // fp16 features, 12 MB
__device__ __align__(128) __half g_Ha[(size_t)NTILE*NSTAGE*2048]; // staged A, 96 MB
__device__ __align__(128) __half g_Bs[(size_t)NSTAGE*8192];       // staged B, 1.2 MB

// ================= helpers =================
__device__ __forceinline__ uint32_t smem_u32(const void* p){
    uint32_t a;
    asm("{ .reg .u64 t; cvta.to.shared.u64 t, %1; cvt.u32.u64 %0, t; }":"=r"(a):"l"(p));
    return a;
}
__device__ __forceinline__ void ldm_x4(uint32_t* r, uint32_t addr){
    asm volatile("ldmatrix.sync.aligned.m8n8.x4.shared.b16 {%0,%1,%2,%3}, [%4];"
        : "=r"(r[0]),"=r"(r[1]),"=r"(r[2]),"=r"(r[3]) : "r"(addr));
}
__device__ __forceinline__ void mma_f16_16x8x16(float* d, const uint32_t* a, const uint32_t* b){
    asm volatile(
        "mma.sync.aligned.m16n8k16.row.col.f32.f16.f16.f32 "
        "{%0,%1,%2,%3}, {%4,%5,%6,%7}, {%8,%9}, {%0,%1,%2,%3};"
        : "+f"(d[0]), "+f"(d[1]), "+f"(d[2]), "+f"(d[3])
        : "r"(a[0]), "r"(a[1]), "r"(a[2]), "r"(a[3]), "r"(b[0]), "r"(b[1]));
}
__device__ __forceinline__ void mbar_wait(uint32_t m, int phase){
    asm volatile(
        "{\n\t.reg .pred P;\n\t"
        "W%=:\n\t"
        "mbarrier.try_wait.parity.acquire.cta.shared::cta.b64 P, [%0], %1, 0x989680;\n\t"
        "@!P bra W%=;\n\t}"
        ::"r"(m),"r"((uint32_t)phase):"memory");
}
__device__ __forceinline__ void bulk_cp(uint32_t dst, const void* src, uint32_t bytes, uint32_t mbar){
    asm volatile(
        "cp.async.bulk.shared::cluster.global.mbarrier::complete_tx::bytes [%0], [%1], %2, [%3];"
        ::"r"(dst), "l"(src), "r"(bytes), "r"(mbar) : "memory");
}
// swizzled byte offset within a stage tile: row (64B rows), granule gq (16B), byte-in-granule bi
__device__ __forceinline__ uint32_t sw_off(int row, int gq, int bi){
    return (uint32_t)((row>>1)*128 + (((((row&1)<<2) + gq) ^ ((row>>1)&7))<<4) + bi);
}

// -------- 0: reset counters --------
__global__ void k_zero() {
    int i  = blockIdx.x * blockDim.x + threadIdx.x;
    int st = gridDim.x * blockDim.x;
    for (int j = i; j < RR*NN; j += st) g_cnt2[j] = 0;
}
// -------- 1: histogram (src,rel) --------
__global__ void k_count(const int* __restrict__ src, const int* __restrict__ rel, int E) {
    int e = blockIdx.x * blockDim.x + threadIdx.x;
    if (e < E) atomicAdd(&g_cnt2[src[e]*RR + rel[e]], 1);
}
// -------- 2: exclusive scan over 220000 (single block) --------
__global__ void k_scan() {
    __shared__ int sh[1024];
    int t = threadIdx.x;
    const int TOT = RR*NN;
    const int C = (TOT + 1023) / 1024;   // 215
    int base = t * C;
    int sum = 0;
    for (int j = 0; j < C; j++) { int idx = base + j; if (idx < TOT) sum += g_cnt2[idx]; }
    sh[t] = sum; __syncthreads();
    for (int d = 1; d < 1024; d <<= 1) {
        int v = (t >= d) ? sh[t-d] : 0;
        __syncthreads();
        sh[t] += v;
        __syncthreads();
    }
    int run = (t > 0) ? sh[t-1] : 0;
    for (int j = 0; j < C; j++) {
        int idx = base + j;
        if (idx < TOT) { g_off2[idx] = run; g_cur2[idx] = run; run += g_cnt2[idx]; }
    }
    if (t == 1023) g_off2[TOT] = sh[1023];
}
// -------- 3: scatter edges, (src,rel)-sorted --------
__global__ void k_scatter(const int* __restrict__ src, const int* __restrict__ rel,
                          const int* __restrict__ dst, int E) {
    int e = blockIdx.x * blockDim.x + threadIdx.x;
    if (e < E) {
        int s = src[e], r = rel[e];
        int pos = atomicAdd(&g_cur2[s*RR + r], 1);
        g_e32[pos] = (uint32_t)(dst[e] | (r << 16));
    }
}
// -------- 3.5: fp16 feature copy --------
__global__ void k_featconv(const float* __restrict__ f) {
    size_t i = (size_t)blockIdx.x * blockDim.x + threadIdx.x;
    if (i < (size_t)NN*IND) g_F16[i] = __float2half_rn(f[i]);
}
// -------- 4: transpose+stage bases [2400,256] -> g_Bs swizzled stages --------
__global__ void k_transpose(const float* __restrict__ B) {
    int idx = blockIdx.x * blockDim.x + threadIdx.x;   // over 2400*256
    if (idx >= KK*OUTD) return;
    int n = idx & 255, k = idx >> 8;
    int st = k >> 5, ks = k & 31;
    unsigned char* bb = (unsigned char*)g_Bs;
    size_t a = (size_t)st*16384 + sw_off(n, ks>>3, (ks&7)*2);
    *(__half*)(bb + a) = __float2half_rn(B[(size_t)k*OUTD + n]);
}
// -------- 5: gather, rel-sorted with deferred flush; writes staged H --------
__global__ void __launch_bounds__(256) k_gather(const float* __restrict__ comps) {
    __shared__ float s_comps[RR*BB];
    __shared__ uint32_t s_ent[64];
    int n = blockIdx.x, t = threadIdx.x;
    if (t < RR*BB) s_comps[t] = comps[t];
    int beg = g_off2[n*RR], end = g_off2[n*RR + RR];
    bool has2 = (t + 256) < IND;
    const __half* F0 = g_F16 + t;
    const __half* F1 = g_F16 + t + 256;

    float a0[BB], a1[BB];
#pragma unroll
    for (int b = 0; b < BB; b++) { a0[b] = 0.f; a1[b] = 0.f; }
    float fs0 = 0.f, fs1 = 0.f;
    int rprev = -1, cnt = 0;
    __syncthreads();

    for (int base = beg; base < end; base += 64) {
        int m = min(64, end - base);
        if (t < m) s_ent[t] = g_e32[base + t];
        __syncthreads();
#pragma unroll 1
        for (int j = 0; j < m; j++) {
            uint32_t e = s_ent[j];
            int r = (int)(e >> 16);
            if (r != rprev) {
                if (cnt > 0) {
                    float val = 1.0f / (float)cnt;
                    float t0 = fs0 * val, t1 = fs1 * val;
                    const float* cp = &s_comps[rprev*BB];
#pragma unroll
                    for (int b = 0; b < BB; b++) { a0[b] += t0*cp[b]; a1[b] += t1*cp[b]; }
                }
                rprev = r; cnt = 0; fs0 = 0.f; fs1 = 0.f;
            }
            size_t d = (size_t)(e & 0xFFFF) * IND;
            fs0 += __half2float(F0[d]);
            if (has2) fs1 += __half2float(F1[d]);
            cnt++;
        }
        __syncthreads();
    }
    if (cnt > 0) {
        float val = 1.0f / (float)cnt;
        float t0 = fs0 * val, t1 = fs1 * val;
        const float* cp = &s_comps[rprev*BB];
#pragma unroll
        for (int b = 0; b < BB; b++) { a0[b] += t0*cp[b]; a1[b] += t1*cp[b]; }
    }

    // write H in staged+swizzled layout
    unsigned char* hb = (unsigned char*)g_Ha;
    size_t tbase = (size_t)(n >> 6) * NSTAGE * 4096;
    int row = n & 63;
#pragma unroll
    for (int b = 0; b < BB; b++) {
        int k0 = b*IND + t;
        *(__half*)(hb + tbase + (size_t)(k0>>5)*4096 + sw_off(row, (k0&31)>>3, (k0&7)*2))
            = __float2half_rn(a0[b]);
        if (has2) {
            int k1 = k0 + 256;
            *(__half*)(hb + tbase + (size_t)(k1>>5)*4096 + sw_off(row, (k1&31)>>3, (k1&7)*2))
                = __float2half_rn(a1[b]);
        }
    }
}

// -------- 6: bulk-copy pipelined fp16 GEMM: out = H @ bases + bias --------
// 128 threads = 4 warps, warp tile 64x64, BM=64, BN=256, 4-stage k32 pipeline.
#define SM_MBAR 0                 // 4 x 8B
#define SM_BIAS 64                // 256 floats
#define SM_A    2048              // 4 x 4096
#define SM_B    18432             // 4 x 16384
#define GSMEM   83968

__global__ void __launch_bounds__(128) k_gemm_bulk(const float* __restrict__ bias,
                                                   float* __restrict__ out) {
    extern __shared__ char smem[];
    uint32_t sb = smem_u32(smem);
    int tid = threadIdx.x, lane = tid & 31, warp = tid >> 5;
    int g = lane >> 2, tg = lane & 3;
    int wn = warp * 64;
    int bm0 = blockIdx.x * 64;
    float* s_bias = (float*)(smem + SM_BIAS);

    if (tid == 0) {
#pragma unroll
        for (int s = 0; s < 4; s++)
            asm volatile("mbarrier.init.shared.b64 [%0], %1;"::"r"(sb + SM_MBAR + s*8),"r"(1u):"memory");
    }
    s_bias[tid] = bias[tid];
    s_bias[tid + 128] = bias[tid + 128];
    __syncthreads();

    const unsigned char* aG = (const unsigned char*)g_Ha + (size_t)blockIdx.x * NSTAGE * 4096;
    const unsigned char* bG = (const unsigned char*)g_Bs;

#define ISSUE(p) do { \
        int _s = (p) & 3; uint32_t _mb = sb + SM_MBAR + _s*8; \
        asm volatile("mbarrier.arrive.expect_tx.shared.b64 _, [%0], %1;"::"r"(_mb),"r"(20480u):"memory"); \
        bulk_cp(sb + SM_A + _s*4096,  aG + (size_t)(p)*4096,  4096u,  _mb); \
        bulk_cp(sb + SM_B + _s*16384, bG + (size_t)(p)*16384, 16384u, _mb); \
    } while (0)

    if (tid == 0) { ISSUE(0); ISSUE(1); ISSUE(2); }

    // ldmatrix lane address components
    int sel = lane >> 3, l8 = lane & 7;
    uint32_t aR[4], bR[4]; int aC[4], aX[4], bC[4], bX[4];
#pragma unroll
    for (int mi = 0; mi < 4; mi++) {
        int row = mi*16 + (sel & 1)*8 + l8;
        aR[mi] = (uint32_t)((row >> 1) * 128);
        aC[mi] = (row & 1) << 2;
        aX[mi] = (row >> 1) & 7;
    }
#pragma unroll
    for (int p = 0; p < 4; p++) {
        int row = wn + p*16 + (sel >> 1)*8 + l8;
        bR[p] = (uint32_t)((row >> 1) * 128);
        bC[p] = (row & 1) << 2;
        bX[p] = (row >> 1) & 7;
    }

    float acc[4][8][4];
#pragma unroll
    for (int mi = 0; mi < 4; mi++)
#pragma unroll
        for (int ni = 0; ni < 8; ni++)
#pragma unroll
            for (int j = 0; j < 4; j++) acc[mi][ni][j] = 0.f;

    for (int kt = 0; kt < NSTAGE; kt++) {
        int s = kt & 3;
        mbar_wait(sb + SM_MBAR + s*8, (kt >> 2) & 1);
        __syncthreads();                        // all warps done with slot (kt+3)&3's old data
        if (tid == 0 && kt + 3 < NSTAGE) ISSUE(kt + 3);

        uint32_t aBase = sb + SM_A + s*4096;
        uint32_t bBase = sb + SM_B + s*16384;
#pragma unroll
        for (int kk = 0; kk < 2; kk++) {        // two k16 steps
            int gA = (sel >> 1) + kk*2;
            int gB = (sel & 1) + kk*2;
            uint32_t a[4][4], b[8][2];
#pragma unroll
            for (int mi = 0; mi < 4; mi++)
                ldm_x4(a[mi], aBase + aR[mi] + (uint32_t)((((aC[mi] + gA) ^ aX[mi]) << 4)));
#pragma unroll
            for (int p = 0; p < 4; p++) {
                uint32_t r[4];
                ldm_x4(r, bBase + bR[p] + (uint32_t)((((bC[p] + gB) ^ bX[p]) << 4)));
                b[2*p][0] = r[0]; b[2*p][1] = r[1];
                b[2*p+1][0] = r[2]; b[2*p+1][1] = r[3];
            }
#pragma unroll
            for (int mi = 0; mi < 4; mi++)
#pragma unroll
                for (int ni = 0; ni < 8; ni++)
                    mma_f16_16x8x16(acc[mi][ni], a[mi], b[ni]);
        }
    }

    // epilogue: + bias
#pragma unroll
    for (int mi = 0; mi < 4; mi++) {
        int row0 = bm0 + mi*16 + g;
#pragma unroll
        for (int ni = 0; ni < 8; ni++) {
            int col = wn + ni*8 + tg*2;
            float b0 = s_bias[col], b1 = s_bias[col + 1];
            if (row0 < NN) {
                float2 v = make_float2(acc[mi][ni][0] + b0, acc[mi][ni][1] + b1);
                *(float2*)&out[(size_t)row0 * OUTD + col] = v;
            }
            if (row0 + 8 < NN) {
                float2 v = make_float2(acc[mi][ni][2] + b0, acc[mi][ni][3] + b1);
                *(float2*)&out[(size_t)(row0 + 8) * OUTD + col] = v;
            }
        }
    }
}

static inline int cdiv(int a, int b) { return (a + b - 1) / b; }

extern "C" void kernel_launch(void* const* d_in, const int* in_sizes, int n_in,
                              void* d_out, int out_size) {
    const float* features = (const float*)d_in[0];
    const float* comps    = (const float*)d_in[1];
    const float* bases    = (const float*)d_in[2];   // flat [2400, 256]
    const float* bias     = (const float*)d_in[3];
    const int*   esrc     = (const int*)d_in[4];
    const int*   erel     = (const int*)d_in[5];
    const int*   edst     = (const int*)d_in[6];
    int E = in_sizes[4];

    cudaFuncSetAttribute(k_gemm_bulk, cudaFuncAttributeMaxDynamicSharedMemorySize, GSMEM);

    k_zero<<<256, 256>>>();
    k_count<<<cdiv(E, 256), 256>>>(esrc, erel, E);
    k_scan<<<1, 1024>>>();
    k_scatter<<<cdiv(E, 256), 256>>>(esrc, erel, edst, E);
    k_featconv<<<cdiv(NN*IND, 256), 256>>>(features);
    k_transpose<<<cdiv(KK*OUTD, 256), 256>>>(bases);
    k_gather<<<NN, 256>>>(comps);
    k_gemm_bulk<<<NTILE, 128, GSMEM>>>(bias, (float*)d_out);
}

// round 7
// speedup vs baseline: 1.7635x; 1.7635x over previous
#include <cuda_runtime.h>
#include <cuda_fp16.h>
#include <stdint.h>

// Problem constants
#define NN   20000
#define RR   11
#define BB   8
#define IND  300
#define OUTD 256
#define EE   640000
#define KK   (BB*IND)            // 2400
#define TOT  (RR*NN)             // 220000
#define NPART ((TOT + 1023)/1024)  // 215

// -------- device scratch --------
__device__ int      g_cnt2[TOT];
__device__ int      g_off2[TOT+1];
__device__ int      g_cur2[TOT];
__device__ int      g_part[NPART];
__device__ uint32_t g_e32[EE];                 // dst | rel<<16
__device__ __half   g_F16[(size_t)NN*IND];     // fp16 features, 12 MB
__device__ __half   g_H[(size_t)NN*KK];        // fp16 H row-major, 96 MB
__device__ __half   g_Bt[OUTD*KK];             // [256, 2400] K-major fp16

// ================= helpers =================
__device__ __forceinline__ void cp16(uint32_t dst, const void* src, int sz){
    asm volatile("cp.async.cg.shared.global [%0], [%1], 16, %2;\n"
                 ::"r"(dst),"l"(src),"r"(sz));
}
__device__ __forceinline__ uint32_t smem_u32(const void* p){
    uint32_t a;
    asm("{ .reg .u64 t; cvta.to.shared.u64 t, %1; cvt.u32.u64 %0, t; }":"=r"(a):"l"(p));
    return a;
}
__device__ __forceinline__ void ldm_x4(uint32_t* r, uint32_t addr){
    asm volatile("ldmatrix.sync.aligned.m8n8.x4.shared.b16 {%0,%1,%2,%3}, [%4];"
        : "=r"(r[0]),"=r"(r[1]),"=r"(r[2]),"=r"(r[3]) : "r"(addr));
}
__device__ __forceinline__ void mma_f16_16x8x16(float* d, const uint32_t* a, const uint32_t* b){
    asm volatile(
        "mma.sync.aligned.m16n8k16.row.col.f32.f16.f16.f32 "
        "{%0,%1,%2,%3}, {%4,%5,%6,%7}, {%8,%9}, {%0,%1,%2,%3};"
        : "+f"(d[0]), "+f"(d[1]), "+f"(d[2]), "+f"(d[3])
        : "r"(a[0]), "r"(a[1]), "r"(a[2]), "r"(a[3]), "r"(b[0]), "r"(b[1]));
}

// -------- 0: reset counters --------
__global__ void k_zero() {
    int i  = blockIdx.x * blockDim.x + threadIdx.x;
    int st = gridDim.x * blockDim.x;
    for (int j = i; j < TOT; j += st) g_cnt2[j] = 0;
}
// -------- 1: histogram (src,rel) --------
__global__ void k_count(const int* __restrict__ src, const int* __restrict__ rel, int E) {
    int e = blockIdx.x * blockDim.x + threadIdx.x;
    if (e < E) atomicAdd(&g_cnt2[src[e]*RR + rel[e]], 1);
}
// -------- 2a: per-block sums --------
__global__ void __launch_bounds__(1024) k_scan1() {
    __shared__ int sh[1024];
    int t = threadIdx.x;
    int i = blockIdx.x * 1024 + t;
    sh[t] = (i < TOT) ? g_cnt2[i] : 0;
    __syncthreads();
    for (int d = 512; d > 0; d >>= 1) {
        if (t < d) sh[t] += sh[t + d];
        __syncthreads();
    }
    if (t == 0) g_part[blockIdx.x] = sh[0];
}
// -------- 2b: exclusive scan of 215 block sums (one block) --------
__global__ void __launch_bounds__(256) k_scan2() {
    __shared__ int sh[256];
    int t = threadIdx.x;
    int v = (t < NPART) ? g_part[t] : 0;
    sh[t] = v; __syncthreads();
    for (int d = 1; d < 256; d <<= 1) {
        int x = (t >= d) ? sh[t - d] : 0;
        __syncthreads();
        sh[t] += x;
        __syncthreads();
    }
    if (t < NPART) g_part[t] = sh[t] - v;   // exclusive
    if (t == 255) g_off2[TOT] = sh[255];
}
// -------- 2c: block-local exclusive scan + block offset --------
__global__ void __launch_bounds__(1024) k_scan3() {
    __shared__ int sh[1024];
    int t = threadIdx.x;
    int i = blockIdx.x * 1024 + t;
    int v = (i < TOT) ? g_cnt2[i] : 0;
    sh[t] = v; __syncthreads();
    for (int d = 1; d < 1024; d <<= 1) {
        int x = (t >= d) ? sh[t - d] : 0;
        __syncthreads();
        sh[t] += x;
        __syncthreads();
    }
    if (i < TOT) {
        int off = g_part[blockIdx.x] + sh[t] - v;
        g_off2[i] = off;
        g_cur2[i] = off;
    }
}
// -------- 3: scatter edges, (src,rel)-sorted --------
__global__ void k_scatter(const int* __restrict__ src, const int* __restrict__ rel,
                          const int* __restrict__ dst, int E) {
    int e = blockIdx.x * blockDim.x + threadIdx.x;
    if (e < E) {
        int s = src[e], r = rel[e];
        int pos = atomicAdd(&g_cur2[s*RR + r], 1);
        g_e32[pos] = (uint32_t)(dst[e] | (r << 16));
    }
}
// -------- 3.5: fp16 feature copy --------
__global__ void k_featconv(const float* __restrict__ f) {
    size_t i = (size_t)blockIdx.x * blockDim.x + threadIdx.x;
    if (i < (size_t)NN*IND) g_F16[i] = __float2half_rn(f[i]);
}
// -------- 4: transpose bases [2400,256] -> g_Bt [256,2400] (fp16) --------
__global__ void k_transpose(const float* __restrict__ B) {
    __shared__ float tile[32][33];
    int bx = blockIdx.x * 32;   // k
    int by = blockIdx.y * 32;   // n
    int x = threadIdx.x, y = threadIdx.y;
    for (int j = y; j < 32; j += 8)
        tile[j][x] = B[(size_t)(bx + j) * OUTD + by + x];
    __syncthreads();
    for (int j = y; j < 32; j += 8)
        g_Bt[(size_t)(by + j) * KK + bx + x] = __float2half_rn(tile[x][j]);
}
// -------- 5: gather, rel-sorted deferred flush; H row-major fp16 --------
__global__ void __launch_bounds__(256) k_gather(const float* __restrict__ comps) {
    __shared__ float s_comps[RR*BB];
    __shared__ uint32_t s_ent[64];
    int n = blockIdx.x, t = threadIdx.x;
    if (t < RR*BB) s_comps[t] = comps[t];
    int beg = g_off2[n*RR], end = g_off2[n*RR + RR];
    bool has2 = (t + 256) < IND;
    const __half* F0 = g_F16 + t;
    const __half* F1 = g_F16 + t + 256;

    float a0[BB], a1[BB];
#pragma unroll
    for (int b = 0; b < BB; b++) { a0[b] = 0.f; a1[b] = 0.f; }
    float fs0 = 0.f, fs1 = 0.f;
    int rprev = -1, cnt = 0;
    __syncthreads();

    for (int base = beg; base < end; base += 64) {
        int m = min(64, end - base);
        if (t < m) s_ent[t] = g_e32[base + t];
        __syncthreads();
#pragma unroll 1
        for (int j = 0; j < m; j++) {
            uint32_t e = s_ent[j];
            int r = (int)(e >> 16);
            if (r != rprev) {
                if (cnt > 0) {
                    float val = 1.0f / (float)cnt;
                    float t0 = fs0 * val, t1 = fs1 * val;
                    const float* cp = &s_comps[rprev*BB];
#pragma unroll
                    for (int b = 0; b < BB; b++) { a0[b] += t0*cp[b]; a1[b] += t1*cp[b]; }
                }
                rprev = r; cnt = 0; fs0 = 0.f; fs1 = 0.f;
            }
            size_t d = (size_t)(e & 0xFFFF) * IND;
            fs0 += __half2float(F0[d]);
            if (has2) fs1 += __half2float(F1[d]);
            cnt++;
        }
        __syncthreads();
    }
    if (cnt > 0) {
        float val = 1.0f / (float)cnt;
        float t0 = fs0 * val, t1 = fs1 * val;
        const float* cp = &s_comps[rprev*BB];
#pragma unroll
        for (int b = 0; b < BB; b++) { a0[b] += t0*cp[b]; a1[b] += t1*cp[b]; }
    }

    __half* h = g_H + (size_t)n * KK;
#pragma unroll
    for (int b = 0; b < BB; b++) {
        h[b*IND + t] = __float2half_rn(a0[b]);
        if (has2) h[b*IND + 256 + t] = __float2half_rn(a1[b]);
    }
}

// -------- 6: fp16 mma.sync + ldmatrix GEMM (R5 verbatim) --------
#define GBM 64
#define GBK 32
#define GSTG 4
#define GTH 256
#define SHV 40
#define STG_A (GBM*SHV*2)            // 5120 B
#define STG_B (OUTD*SHV*2)           // 20480 B
#define STG_ALL (STG_A+STG_B)        // 25600 B
#define GSMEM (GSTG*STG_ALL)         // 102400 B

__global__ void __launch_bounds__(GTH, 2) k_gemm_mma(const float* __restrict__ bias,
                                                     float* __restrict__ out) {
    extern __shared__ char smem[];
    uint32_t sb = smem_u32(smem);
    int tid  = threadIdx.x;
    int lane = tid & 31, warp = tid >> 5;
    int g  = lane >> 2, tg = lane & 3;
    int wm = (warp >> 2) * 32;
    int wn = (warp & 3) * 64;
    int bm0 = blockIdx.x * GBM;

    int arow = tid >> 2, q = tid & 3;
    const __half* aSrc = g_H + (size_t)min(bm0 + arow, NN-1) * KK + q * 8;
    int aSz = (bm0 + arow < NN) ? 16 : 0;
    uint32_t aDst = (uint32_t)(arow * SHV + q * 8) * 2;
    const __half* bSrc[4]; uint32_t bDst[4];
#pragma unroll
    for (int i = 0; i < 4; i++) {
        int brow = (tid >> 2) + i * 64;
        bSrc[i] = g_Bt + (size_t)brow * KK + q * 8;
        bDst[i] = (uint32_t)(brow * SHV + q * 8) * 2;
    }

#define ISSUE_STAGE(kt, s) do { \
        uint32_t base = sb + (s) * STG_ALL; \
        size_t ko = (size_t)(kt) * GBK; \
        cp16(base + aDst, aSrc + ko, aSz); \
        _Pragma("unroll") for (int i = 0; i < 4; i++) \
            cp16(base + STG_A + bDst[i], bSrc[i] + ko, 16); \
        asm volatile("cp.async.commit_group;":::"memory"); \
    } while (0)

    int sel = lane >> 3, l8 = lane & 7;
    uint32_t aOff[2], bOff[4];
#pragma unroll
    for (int mi = 0; mi < 2; mi++)
        aOff[mi] = (uint32_t)((wm + mi*16 + (sel & 1)*8 + l8) * SHV + (sel >> 1)*8) * 2;
#pragma unroll
    for (int p = 0; p < 4; p++)
        bOff[p] = (uint32_t)((wn + p*16 + (sel >> 1)*8 + l8) * SHV + (sel & 1)*8) * 2;

    float acc[2][8][4];
#pragma unroll
    for (int mi = 0; mi < 2; mi++)
#pragma unroll
        for (int ni = 0; ni < 8; ni++)
#pragma unroll
            for (int j = 0; j < 4; j++) acc[mi][ni][j] = 0.f;

    ISSUE_STAGE(0, 0);
    ISSUE_STAGE(1, 1);
    ISSUE_STAGE(2, 2);

    const int KT = KK / GBK;  // 75
    for (int kt = 0; kt < KT; kt++) {
        int s = kt & (GSTG - 1);
        asm volatile("cp.async.wait_group %0;" :: "n"(GSTG - 2) : "memory");
        __syncthreads();
        if (kt + 3 < KT) ISSUE_STAGE(kt + 3, (kt + 3) & (GSTG - 1));
        else asm volatile("cp.async.commit_group;":::"memory");

        uint32_t baseA = sb + s * STG_ALL;
        uint32_t baseB = baseA + STG_A;
#pragma unroll
        for (int kk = 0; kk < GBK; kk += 16) {
            uint32_t a[2][4], b[8][2];
#pragma unroll
            for (int mi = 0; mi < 2; mi++)
                ldm_x4(a[mi], baseA + aOff[mi] + kk*2);
#pragma unroll
            for (int p = 0; p < 4; p++) {
                uint32_t r[4];
                ldm_x4(r, baseB + bOff[p] + kk*2);
                b[2*p][0] = r[0]; b[2*p][1] = r[1];
                b[2*p+1][0] = r[2]; b[2*p+1][1] = r[3];
            }
#pragma unroll
            for (int mi = 0; mi < 2; mi++)
#pragma unroll
                for (int ni = 0; ni < 8; ni++)
                    mma_f16_16x8x16(acc[mi][ni], a[mi], b[ni]);
        }
    }

#pragma unroll
    for (int mi = 0; mi < 2; mi++) {
        int row0 = bm0 + wm + mi * 16 + g;
#pragma unroll
        for (int ni = 0; ni < 8; ni++) {
            int col = wn + ni * 8 + tg * 2;
            float b0 = bias[col], b1 = bias[col + 1];
            if (row0 < NN) {
                float2 v = make_float2(acc[mi][ni][0] + b0, acc[mi][ni][1] + b1);
                *(float2*)&out[(size_t)row0 * OUTD + col] = v;
            }
            if (row0 + 8 < NN) {
                float2 v = make_float2(acc[mi][ni][2] + b0, acc[mi][ni][3] + b1);
                *(float2*)&out[(size_t)(row0 + 8) * OUTD + col] = v;
            }
        }
    }
}

static inline int cdiv(int a, int b) { return (a + b - 1) / b; }

extern "C" void kernel_launch(void* const* d_in, const int* in_sizes, int n_in,
                              void* d_out, int out_size) {
    const float* features = (const float*)d_in[0];
    const float* comps    = (const float*)d_in[1];
    const float* bases    = (const float*)d_in[2];   // flat [2400, 256]
    const float* bias     = (const float*)d_in[3];
    const int*   esrc     = (const int*)d_in[4];
    const int*   erel     = (const int*)d_in[5];
    const int*   edst     = (const int*)d_in[6];
    int E = in_sizes[4];

    cudaFuncSetAttribute(k_gemm_mma, cudaFuncAttributeMaxDynamicSharedMemorySize, GSMEM);

    k_zero<<<256, 256>>>();
    k_count<<<cdiv(E, 256), 256>>>(esrc, erel, E);
    k_scan1<<<NPART, 1024>>>();
    k_scan2<<<1, 256>>>();
    k_scan3<<<NPART, 1024>>>();
    k_scatter<<<cdiv(E, 256), 256>>>(esrc, erel, edst, E);
    k_featconv<<<cdiv(NN*IND, 256), 256>>>(features);
    dim3 tgrid(KK/32, OUTD/32), tblk(32, 8);
    k_transpose<<<tgrid, tblk>>>(bases);
    k_gather<<<NN, 256>>>(comps);
    k_gemm_mma<<<cdiv(NN, GBM), GTH, GSMEM>>>(bias, (float*)d_out);
}

// round 8
// speedup vs baseline: 1.9139x; 1.0853x over previous
#include <cuda_runtime.h>
#include <cuda_fp16.h>
#include <stdint.h>

// Problem constants
#define NN   20000
#define RR   11
#define BB   8
#define IND  300
#define OUTD 256
#define EE   640000
#define KK   (BB*IND)              // 2400
#define TOT  (RR*NN)               // 220000
#define NPART ((TOT + 1023)/1024)  // 215
#define NSTAGE 75                  // KK/32
#define NTILE  313                 // ceil(NN/64)

// -------- device scratch --------
__device__ int      g_cnt2[TOT];
__device__ int      g_off2[TOT+1];
__device__ int      g_cur2[TOT];
__device__ int      g_part[NPART];
__device__ uint32_t g_e32[EE];                 // dst | rel<<16
__device__ __half   g_F16[(size_t)NN*IND];     // fp16 features, 12 MB
__device__ __align__(128) __half g_Ha[(size_t)NTILE*NSTAGE*2048]; // staged A tiles, 96 MB
__device__ __align__(128) __half g_Bs[(size_t)NSTAGE*8192];       // staged B tiles, 1.2 MB

// ================= helpers =================
__device__ __forceinline__ uint32_t smem_u32(const void* p){
    uint32_t a;
    asm("{ .reg .u64 t; cvta.to.shared.u64 t, %1; cvt.u32.u64 %0, t; }":"=r"(a):"l"(p));
    return a;
}
__device__ __forceinline__ void ldm_x4(uint32_t* r, uint32_t addr){
    asm volatile("ldmatrix.sync.aligned.m8n8.x4.shared.b16 {%0,%1,%2,%3}, [%4];"
        : "=r"(r[0]),"=r"(r[1]),"=r"(r[2]),"=r"(r[3]) : "r"(addr));
}
__device__ __forceinline__ void mma_f16_16x8x16(float* d, const uint32_t* a, const uint32_t* b){
    asm volatile(
        "mma.sync.aligned.m16n8k16.row.col.f32.f16.f16.f32 "
        "{%0,%1,%2,%3}, {%4,%5,%6,%7}, {%8,%9}, {%0,%1,%2,%3};"
        : "+f"(d[0]), "+f"(d[1]), "+f"(d[2]), "+f"(d[3])
        : "r"(a[0]), "r"(a[1]), "r"(a[2]), "r"(a[3]), "r"(b[0]), "r"(b[1]));
}
__device__ __forceinline__ void mbar_wait(uint32_t m, int phase){
    asm volatile(
        "{\n\t.reg .pred P;\n\t"
        "W%=:\n\t"
        "mbarrier.try_wait.parity.acquire.cta.shared::cta.b64 P, [%0], %1, 0x989680;\n\t"
        "@!P bra W%=;\n\t}"
        ::"r"(m),"r"((uint32_t)phase):"memory");
}
__device__ __forceinline__ void bulk_cp(uint32_t dst, const void* src, uint32_t bytes, uint32_t mbar){
    asm volatile(
        "cp.async.bulk.shared::cluster.global.mbarrier::complete_tx::bytes [%0], [%1], %2, [%3];"
        ::"r"(dst), "l"(src), "r"(bytes), "r"(mbar) : "memory");
}
// swizzled byte offset inside a 64-row stage tile (rows of 32 halves = 64B):
// row pair packed per 128B line; granule q (16B) XORed by line index.
__device__ __forceinline__ uint32_t sw_off(int row, int gq, int bi){
    return (uint32_t)((row>>1)*128 + (((((row&1)<<2) + gq) ^ ((row>>1)&7))<<4) + bi);
}

// -------- 0: reset counters --------
__global__ void k_zero() {
    int i  = blockIdx.x * blockDim.x + threadIdx.x;
    int st = gridDim.x * blockDim.x;
    for (int j = i; j < TOT; j += st) g_cnt2[j] = 0;
}
// -------- 1: histogram (src,rel) --------
__global__ void k_count(const int* __restrict__ src, const int* __restrict__ rel, int E) {
    int e = blockIdx.x * blockDim.x + threadIdx.x;
    if (e < E) atomicAdd(&g_cnt2[src[e]*RR + rel[e]], 1);
}
// -------- 2a: per-block sums --------
__global__ void __launch_bounds__(1024) k_scan1() {
    __shared__ int sh[1024];
    int t = threadIdx.x;
    int i = blockIdx.x * 1024 + t;
    sh[t] = (i < TOT) ? g_cnt2[i] : 0;
    __syncthreads();
    for (int d = 512; d > 0; d >>= 1) {
        if (t < d) sh[t] += sh[t + d];
        __syncthreads();
    }
    if (t == 0) g_part[blockIdx.x] = sh[0];
}
// -------- 2b: exclusive scan of block sums --------
__global__ void __launch_bounds__(256) k_scan2() {
    __shared__ int sh[256];
    int t = threadIdx.x;
    int v = (t < NPART) ? g_part[t] : 0;
    sh[t] = v; __syncthreads();
    for (int d = 1; d < 256; d <<= 1) {
        int x = (t >= d) ? sh[t - d] : 0;
        __syncthreads();
        sh[t] += x;
        __syncthreads();
    }
    if (t < NPART) g_part[t] = sh[t] - v;
    if (t == 255) g_off2[TOT] = sh[255];
}
// -------- 2c: block-local scan + offset --------
__global__ void __launch_bounds__(1024) k_scan3() {
    __shared__ int sh[1024];
    int t = threadIdx.x;
    int i = blockIdx.x * 1024 + t;
    int v = (i < TOT) ? g_cnt2[i] : 0;
    sh[t] = v; __syncthreads();
    for (int d = 1; d < 1024; d <<= 1) {
        int x = (t >= d) ? sh[t - d] : 0;
        __syncthreads();
        sh[t] += x;
        __syncthreads();
    }
    if (i < TOT) {
        int off = g_part[blockIdx.x] + sh[t] - v;
        g_off2[i] = off;
        g_cur2[i] = off;
    }
}
// -------- 3: scatter edges, (src,rel)-sorted --------
__global__ void k_scatter(const int* __restrict__ src, const int* __restrict__ rel,
                          const int* __restrict__ dst, int E) {
    int e = blockIdx.x * blockDim.x + threadIdx.x;
    if (e < E) {
        int s = src[e], r = rel[e];
        int pos = atomicAdd(&g_cur2[s*RR + r], 1);
        g_e32[pos] = (uint32_t)(dst[e] | (r << 16));
    }
}
// -------- 3.5: fp16 feature copy --------
__global__ void k_featconv(const float* __restrict__ f) {
    size_t i = (size_t)blockIdx.x * blockDim.x + threadIdx.x;
    if (i < (size_t)NN*IND) g_F16[i] = __float2half_rn(f[i]);
}
// -------- 4: bases [2400,256] -> staged swizzled g_Bs --------
__global__ void k_transpose(const float* __restrict__ B) {
    int idx = blockIdx.x * blockDim.x + threadIdx.x;   // over 2400*256
    if (idx >= KK*OUTD) return;
    int n = idx & 255, k = idx >> 8;
    int st = k >> 5, ks = k & 31;
    unsigned char* bb = (unsigned char*)g_Bs;
    size_t a = (size_t)st*16384 + sw_off(n, ks>>3, (ks&7)*2);
    *(__half*)(bb + a) = __float2half_rn(B[(size_t)k*OUTD + n]);
}
// -------- 5: gather (dedup, 1 col/thread, prefetch); writes staged H --------
__global__ void __launch_bounds__(320) k_gather(const float* __restrict__ comps) {
    __shared__ float    s_comps[RR*BB];
    __shared__ uint32_t s_ent[64];
    __shared__ __half   s_h[KK];          // 4.8 KB staging
    int n = blockIdx.x, t = threadIdx.x;
    if (t < RR*BB) s_comps[t] = comps[t];
    int beg = g_off2[n*RR], end = g_off2[n*RR + RR];
    bool act = t < IND;
    const __half* F = g_F16 + t;

    float a[BB];
#pragma unroll
    for (int b = 0; b < BB; b++) a[b] = 0.f;
    float fs = 0.f;
    int rprev = -1, cnt = 0;
    float fcur = 0.f;
    bool havecur = false;
    __syncthreads();

    for (int base = beg; base < end; base += 64) {
        int m = min(64, end - base);
        if (t < m) s_ent[t] = g_e32[base + t];
        __syncthreads();
        if (!havecur && m > 0) {
            fcur = act ? __half2float(F[(size_t)(s_ent[0] & 0xFFFF) * IND]) : 0.f;
            havecur = true;
        }
#pragma unroll 1
        for (int j = 0; j < m; j++) {
            // prefetch next edge's feature (within batch)
            float fnext = 0.f;
            if (j + 1 < m && act)
                fnext = __half2float(F[(size_t)(s_ent[j+1] & 0xFFFF) * IND]);
            uint32_t e = s_ent[j];
            int r = (int)(e >> 16);
            if (r != rprev) {
                if (cnt > 0) {
                    float t0 = fs * (1.0f / (float)cnt);
                    const float* cp = &s_comps[rprev*BB];
#pragma unroll
                    for (int b = 0; b < BB; b++) a[b] += t0*cp[b];
                }
                rprev = r; cnt = 0; fs = 0.f;
            }
            fs += fcur;
            cnt++;
            fcur = fnext;
        }
        havecur = false;   // next batch reloads first edge
        __syncthreads();
    }
    if (cnt > 0) {
        float t0 = fs * (1.0f / (float)cnt);
        const float* cp = &s_comps[rprev*BB];
#pragma unroll
        for (int b = 0; b < BB; b++) a[b] += t0*cp[b];
    }

    // stage into smem (k = b*IND + t), then cooperative 16B swizzled stores
    if (act) {
#pragma unroll
        for (int b = 0; b < BB; b++) s_h[b*IND + t] = __float2half_rn(a[b]);
    }
    __syncthreads();
    unsigned char* hb = (unsigned char*)g_Ha + (size_t)(n >> 6) * NSTAGE * 4096;
    int row = n & 63;
    if (t < KK/8) {                  // 300 granules of 16B
        int k0 = t * 8;
        int st = k0 >> 5, q = (k0 >> 3) & 3;
        uint4 v = *(const uint4*)&s_h[k0];
        *(uint4*)(hb + (size_t)st*4096 + sw_off(row, q, 0)) = v;
    }
}

// -------- 6: bulk-copy pipelined fp16 GEMM: out = H @ bases + bias --------
// 256 threads = 8 warps (2x4), warp tile 32x64, BM=64, BN=256, 4-stage k32.
#define SM_MBAR 0                 // 4 x 8B
#define SM_BIAS 64                // 256 floats
#define SM_A    2048              // 4 x 4096
#define SM_B    18432             // 4 x 16384
#define GSMEM   83968

__global__ void __launch_bounds__(256) k_gemm_bulk(const float* __restrict__ bias,
                                                   float* __restrict__ out) {
    extern __shared__ char smem[];
    uint32_t sb = smem_u32(smem);
    int tid = threadIdx.x, lane = tid & 31, warp = tid >> 5;
    int g = lane >> 2, tg = lane & 3;
    int wm = (warp >> 2) * 32;       // 0 / 32
    int wn = (warp & 3) * 64;        // 0,64,128,192
    int bm0 = blockIdx.x * 64;
    float* s_bias = (float*)(smem + SM_BIAS);

    if (tid == 0) {
#pragma unroll
        for (int s = 0; s < 4; s++)
            asm volatile("mbarrier.init.shared.b64 [%0], %1;"::"r"(sb + SM_MBAR + s*8),"r"(1u):"memory");
    }
    s_bias[tid] = bias[tid];
    __syncthreads();

    const unsigned char* aG = (const unsigned char*)g_Ha + (size_t)blockIdx.x * NSTAGE * 4096;
    const unsigned char* bG = (const unsigned char*)g_Bs;

#define ISSUE(p) do { \
        int _s = (p) & 3; uint32_t _mb = sb + SM_MBAR + _s*8; \
        asm volatile("mbarrier.arrive.expect_tx.shared.b64 _, [%0], %1;"::"r"(_mb),"r"(20480u):"memory"); \
        bulk_cp(sb + SM_A + _s*4096,  aG + (size_t)(p)*4096,  4096u,  _mb); \
        bulk_cp(sb + SM_B + _s*16384, bG + (size_t)(p)*16384, 16384u, _mb); \
    } while (0)

    if (tid == 0) { ISSUE(0); ISSUE(1); ISSUE(2); }

    // ldmatrix lane address components (swizzled stage layout)
    int sel = lane >> 3, l8 = lane & 7;
    uint32_t aR[2]; int aC[2], aX[2];
#pragma unroll
    for (int mi = 0; mi < 2; mi++) {
        int row = wm + mi*16 + (sel & 1)*8 + l8;
        aR[mi] = (uint32_t)((row >> 1) * 128);
        aC[mi] = (row & 1) << 2;
        aX[mi] = (row >> 1) & 7;
    }
    uint32_t bR[4]; int bC[4], bX[4];
#pragma unroll
    for (int p = 0; p < 4; p++) {
        int row = wn + p*16 + (sel >> 1)*8 + l8;
        bR[p] = (uint32_t)((row >> 1) * 128);
        bC[p] = (row & 1) << 2;
        bX[p] = (row >> 1) & 7;
    }

    float acc[2][8][4];
#pragma unroll
    for (int mi = 0; mi < 2; mi++)
#pragma unroll
        for (int ni = 0; ni < 8; ni++)
#pragma unroll
            for (int j = 0; j < 4; j++) acc[mi][ni][j] = 0.f;

    for (int kt = 0; kt < NSTAGE; kt++) {
        int s = kt & 3;
        mbar_wait(sb + SM_MBAR + s*8, (kt >> 2) & 1);
        __syncthreads();                     // all warps finished with slot (kt+3)&3
        if (tid == 0 && kt + 3 < NSTAGE) ISSUE(kt + 3);

        uint32_t aBase = sb + SM_A + s*4096;
        uint32_t bBase = sb + SM_B + s*16384;
#pragma unroll
        for (int kk = 0; kk < 2; kk++) {     // two k16 steps
            int gA = (sel >> 1) + kk*2;
            int gB = (sel & 1) + kk*2;
            uint32_t a[2][4], b[8][2];
#pragma unroll
            for (int mi = 0; mi < 2; mi++)
                ldm_x4(a[mi], aBase + aR[mi] + (uint32_t)(((aC[mi] + gA) ^ aX[mi]) << 4));
#pragma unroll
            for (int p = 0; p < 4; p++) {
                uint32_t r[4];
                ldm_x4(r, bBase + bR[p] + (uint32_t)(((bC[p] + gB) ^ bX[p]) << 4));
                b[2*p][0] = r[0]; b[2*p][1] = r[1];
                b[2*p+1][0] = r[2]; b[2*p+1][1] = r[3];
            }
#pragma unroll
            for (int mi = 0; mi < 2; mi++)
#pragma unroll
                for (int ni = 0; ni < 8; ni++)
                    mma_f16_16x8x16(acc[mi][ni], a[mi], b[ni]);
        }
    }

    // epilogue: + bias
#pragma unroll
    for (int mi = 0; mi < 2; mi++) {
        int row0 = bm0 + wm + mi*16 + g;
#pragma unroll
        for (int ni = 0; ni < 8; ni++) {
            int col = wn + ni*8 + tg*2;
            float b0 = s_bias[col], b1 = s_bias[col + 1];
            if (row0 < NN) {
                float2 v = make_float2(acc[mi][ni][0] + b0, acc[mi][ni][1] + b1);
                *(float2*)&out[(size_t)row0 * OUTD + col] = v;
            }
            if (row0 + 8 < NN) {
                float2 v = make_float2(acc[mi][ni][2] + b0, acc[mi][ni][3] + b1);
                *(float2*)&out[(size_t)(row0 + 8) * OUTD + col] = v;
            }
        }
    }
}

static inline int cdiv(int a, int b) { return (a + b - 1) / b; }

extern "C" void kernel_launch(void* const* d_in, const int* in_sizes, int n_in,
                              void* d_out, int out_size) {
    const float* features = (const float*)d_in[0];
    const float* comps    = (const float*)d_in[1];
    const float* bases    = (const float*)d_in[2];   // flat [2400, 256]
    const float* bias     = (const float*)d_in[3];
    const int*   esrc     = (const int*)d_in[4];
    const int*   erel     = (const int*)d_in[5];
    const int*   edst     = (const int*)d_in[6];
    int E = in_sizes[4];

    cudaFuncSetAttribute(k_gemm_bulk, cudaFuncAttributeMaxDynamicSharedMemorySize, GSMEM);

    k_zero<<<256, 256>>>();
    k_count<<<cdiv(E, 256), 256>>>(esrc, erel, E);
    k_scan1<<<NPART, 1024>>>();
    k_scan2<<<1, 256>>>();
    k_scan3<<<NPART, 1024>>>();
    k_scatter<<<cdiv(E, 256), 256>>>(esrc, erel, edst, E);
    k_featconv<<<cdiv(NN*IND, 256), 256>>>(features);
    k_transpose<<<cdiv(KK*OUTD, 256), 256>>>(bases);
    k_gather<<<NN, 320>>>(comps);
    k_gemm_bulk<<<NTILE, 256, GSMEM>>>(bias, (float*)d_out);
}